// round 16
// baseline (speedup 1.0000x reference)
#include <cuda_runtime.h>
#include <cuda_fp16.h>
#include <math.h>

// Problem dims
#define Bb   64
#define Tt   512
#define Dd   256
#define Hh   1024
#define Gg   4096          // 4*H
#define Mm   32768         // B*T
#define NCTA 64            // lstm persistent CTAs (each owns 64 gate-cols)

// ---------------- scratch (__device__ globals; no dynamic allocation) ----------
__device__ float d_xg[(size_t)Tt * Gg * Bb];      // [t][m=j*4+g][b]   512 MB
__device__ uint4 d_Afh[(size_t)128 * 2 * 64 * 32];    // Wh fp16 A-frags, 8 MB
__device__ uint4 d_Axfh[(size_t)32 * 8 * 16 * 32];    // Wx fp16 A-frags, 2 MB
__device__ float d_Wof[(size_t)Dd * Hh];          // Wout tf32 A-fragments, 1 MB
__device__ float d_hsJ[(size_t)Hh * Mm];          // [j][m'] , m'=t*64+b   128 MB
__device__ float d_outT[(size_t)Dd * Mm];         // out head, [d][m']     32 MB
__device__ unsigned d_h2h[2 * 512 * Bb];          // double-buffered h, half2 [buf][k/2][b]
__device__ unsigned d_bcount;

__device__ __forceinline__ unsigned tf32r(float x)
{
    unsigned u;
    asm("cvt.rna.tf32.f32 %0, %1;" : "=r"(u) : "f"(x));
    return u;
}
__device__ __forceinline__ float tanh_ap(float x)
{
    float y;
    asm("tanh.approx.f32 %0, %1;" : "=f"(y) : "f"(x));
    return y;
}
__device__ __forceinline__ unsigned pkh2(float lo, float hi)
{
    __half2 h = __floats2half2_rn(lo, hi);
    return *(unsigned*)&h;
}
// fast (MUFU) sigmoid / tanh: rel err ~2^-21, negligible vs fp16-h noise
__device__ __forceinline__ float sigm(float x)
{
    return __fdividef(1.f, 1.f + __expf(-x));
}
__device__ __forceinline__ float tanh_fast(float x)
{
    return __fdividef(2.f, 1.f + __expf(-2.f * x)) - 1.f;
}

// tf32 mma: D(m16n8) += A(m16k8) * B(k8n8)
#define MMA_TF32(d, a0, a1, a2, a3, b0, b1)                                     \
    asm volatile("mma.sync.aligned.m16n8k8.row.col.f32.tf32.tf32.f32 "          \
                 "{%0,%1,%2,%3}, {%4,%5,%6,%7}, {%8,%9}, {%0,%1,%2,%3};"        \
                 : "+f"(d[0]), "+f"(d[1]), "+f"(d[2]), "+f"(d[3])               \
                 : "r"(a0), "r"(a1), "r"(a2), "r"(a3), "r"(b0), "r"(b1))

// fp16 mma: D(m16n8) += A(m16k16) * B(k16n8), fp32 accum
#define MMA_F16(d, a0, a1, a2, a3, b0, b1)                                      \
    asm volatile("mma.sync.aligned.m16n8k16.row.col.f32.f16.f16.f32 "           \
                 "{%0,%1,%2,%3}, {%4,%5,%6,%7}, {%8,%9}, {%0,%1,%2,%3};"        \
                 : "+f"(d[0]), "+f"(d[1]), "+f"(d[2]), "+f"(d[3])               \
                 : "r"(a0), "r"(a1), "r"(a2), "r"(a3), "r"(b0), "r"(b1))

// ---------------- init: zero h state, reset barrier -----------------------------
__global__ void init_k()
{
    int i = blockIdx.x * blockDim.x + threadIdx.x;
    if (i < 2 * 512 * Bb) d_h2h[i] = 0u;
    if (i == 0) d_bcount = 0u;
}

// ---------------- combined weight-fragment packing ------------------------------
// blocks [0,2048): Wh fp16   [2048,2560): Wx fp16   [2560,2816): Wout tf32
__global__ void pack_all(const float* __restrict__ Wh, const float* __restrict__ Wx,
                         const float* __restrict__ Wo)
{
    int blk = blockIdx.x;
    if (blk < 2048) {
        // Wh fp16 A frag: uint4 i = ((cb*2+ms)*64 + k16)*32 + lane   (cb: 32-col block)
        size_t i = (size_t)blk * 256 + threadIdx.x;   // 524,288 total
        int lane = i & 31;
        int k16  = (i >> 5) & 63;
        int ms   = (i >> 11) & 1;
        int cb   = (int)(i >> 12);
        int g = lane >> 2, tig = lane & 3;
        int m1 = ms * 16 + g, m2 = m1 + 8;
        int r1 = (m1 & 3) * Hh + cb * 8 + (m1 >> 2);
        int r2 = (m2 & 3) * Hh + cb * 8 + (m2 >> 2);
        int k0 = k16 * 16 + tig * 2;
        uint4 v;
        v.x = pkh2(Wh[(size_t)r1 * Hh + k0],     Wh[(size_t)r1 * Hh + k0 + 1]);
        v.y = pkh2(Wh[(size_t)r2 * Hh + k0],     Wh[(size_t)r2 * Hh + k0 + 1]);
        v.z = pkh2(Wh[(size_t)r1 * Hh + k0 + 8], Wh[(size_t)r1 * Hh + k0 + 9]);
        v.w = pkh2(Wh[(size_t)r2 * Hh + k0 + 8], Wh[(size_t)r2 * Hh + k0 + 9]);
        d_Afh[i] = v;
    } else if (blk < 2560) {
        // Wx fp16 A frag: uint4 i = ((gb*8+ws)*16 + k16)*32 + lane
        size_t i = (size_t)(blk - 2048) * 256 + threadIdx.x;  // 131,072 total
        int lane = i & 31;
        int k16  = (i >> 5) & 15;
        int ws   = (i >> 9) & 7;
        int gb   = (int)(i >> 12);
        int g = lane >> 2, tig = lane & 3;
        int m1 = gb * 128 + ws * 16 + g, m2 = m1 + 8;
        int r1 = (m1 & 3) * Hh + (m1 >> 2);
        int r2 = (m2 & 3) * Hh + (m2 >> 2);
        int k0 = k16 * 16 + tig * 2;
        uint4 v;
        v.x = pkh2(Wx[(size_t)r1 * Dd + k0],     Wx[(size_t)r1 * Dd + k0 + 1]);
        v.y = pkh2(Wx[(size_t)r2 * Dd + k0],     Wx[(size_t)r2 * Dd + k0 + 1]);
        v.z = pkh2(Wx[(size_t)r1 * Dd + k0 + 8], Wx[(size_t)r1 * Dd + k0 + 9]);
        v.w = pkh2(Wx[(size_t)r2 * Dd + k0 + 8], Wx[(size_t)r2 * Dd + k0 + 9]);
        d_Axfh[i] = v;
    } else {
        size_t i = (size_t)(blk - 2560) * 256 + threadIdx.x;
        int lane = i & 31;
        int k8   = (i >> 5) & 127;
        int s    = (int)(i >> 12);
        int g = lane >> 2, tig = lane & 3;
        int d1 = s * 16 + g, d2 = d1 + 8;
        int k0 = k8 * 8;
        float4 v;
        v.x = __uint_as_float(tf32r(Wo[(size_t)d1 * Hh + k0 + tig]));
        v.y = __uint_as_float(tf32r(Wo[(size_t)d2 * Hh + k0 + tig]));
        v.z = __uint_as_float(tf32r(Wo[(size_t)d1 * Hh + k0 + tig + 4]));
        v.w = __uint_as_float(tf32r(Wo[(size_t)d2 * Hh + k0 + tig + 4]));
        ((float4*)d_Wof)[i] = v;
    }
}

// ---------------- GEMM 1 (fp16 mma): xg[t][m][b] = inputs . Wx^T + bx + bh ------
// Inputs staged as fp16 [b][k], row = 256 halfs, PITCH 264 halfs.
#define XPH 264
__global__ void __launch_bounds__(256) gemm_xg_mma(
    const float* __restrict__ inp, const float* __restrict__ bx,
    const float* __restrict__ bh)
{
    extern __shared__ __align__(16) unsigned short hsmx[];   // 2 * 64 * XPH halfs
    const int tid = threadIdx.x, w = tid >> 5, lane = tid & 31;
    const int g = lane >> 2, tig = lane & 3;
    const int gb = blockIdx.x;
    const int m1 = gb * 128 + w * 16 + g, m2 = m1 + 8;
    const int r1 = (m1 & 3) * Hh + (m1 >> 2), r2 = (m2 & 3) * Hh + (m2 >> 2);
    const float bias1 = bx[r1] + bh[r1];
    const float bias2 = bx[r2] + bh[r2];
    const uint4* Af = d_Axfh + ((size_t)(gb * 8 + w) * 16) * 32 + lane;
    const int brow = w * 8 + (lane >> 2);
    const int bq = lane & 3;

    for (int t0 = blockIdx.y * 2; t0 < Tt; t0 += 8) {
#pragma unroll
        for (int sl = 0; sl < 2; sl++) {
            const float4* src = (const float4*)(inp + ((size_t)brow * Tt + t0 + sl) * Dd);
            unsigned short* dst = hsmx + sl * 64 * XPH + brow * XPH;
#pragma unroll
            for (int i2 = 0; i2 < 16; i2++) {
                float4 v = __ldg(&src[i2 * 4 + bq]);
                uint2 p;
                p.x = pkh2(v.x, v.y);
                p.y = pkh2(v.z, v.w);
                *(uint2*)&dst[(i2 * 4 + bq) * 4] = p;
            }
        }
        __syncthreads();

        float acc[2][8][4];
#pragma unroll
        for (int sl = 0; sl < 2; sl++)
#pragma unroll
            for (int nb = 0; nb < 8; nb++)
#pragma unroll
                for (int q = 0; q < 4; q++) acc[sl][nb][q] = 0.f;

#pragma unroll 4
        for (int k16 = 0; k16 < 16; k16++) {
            uint4 a4 = __ldg(&Af[k16 * 32]);
            const int k0 = k16 * 16;
#pragma unroll
            for (int nb = 0; nb < 8; nb++) {
#pragma unroll
                for (int sl = 0; sl < 2; sl++) {
                    const unsigned short* bp =
                        hsmx + sl * 64 * XPH + (nb * 8 + g) * XPH + k0 + tig * 2;
                    unsigned b0 = *(const unsigned*)bp;
                    unsigned b1 = *(const unsigned*)(bp + 8);
                    MMA_F16(acc[sl][nb], a4.x, a4.y, a4.z, a4.w, b0, b1);
                }
            }
        }
#pragma unroll
        for (int sl = 0; sl < 2; sl++) {
            int t = t0 + sl;
#pragma unroll
            for (int nb = 0; nb < 8; nb++) {
                *(float2*)&d_xg[((size_t)t * Gg + m1) * 64 + nb * 8 + tig * 2] =
                    make_float2(acc[sl][nb][0] + bias1, acc[sl][nb][1] + bias1);
                *(float2*)&d_xg[((size_t)t * Gg + m2) * 64 + nb * 8 + tig * 2] =
                    make_float2(acc[sl][nb][2] + bias2, acc[sl][nb][3] + bias2);
            }
        }
        __syncthreads();
    }
}

// ---------------- persistent LSTM recurrence (fp16 mma, 64 CTAs x 2x tile) ------
// 64 CTAs x 512 thr (16 warps).  CTA owns 64 gate-cols (16 j), N=64, K=1024.
// Per step: cp.async the ENTIRE h (144 KB), one sync, then each warp streams
// its k-HALF for its m-half (cbw) with both m-strips: 32 k16 x (2 A-LDG +
// 4 B-LDS + 4 MMAs) = 128 MMAs/warp.  Warp w: kh=w>>3, cbw=(w>>2)&1,
// n0=(w&3)*16.  Two D buffers (per k-half, 64 rows) summed in the pointwise
// (2 (j,b) pairs / thread).  Split grid barrier.
#define HP2 72
#define HS_FULL (512 * HP2)                  // unsigned words (144 KB)
#define DS_P 68
#define DS_H (64 * DS_P)                     // floats per k-half buffer
#define DS_SZ (2 * DS_H)                     // floats
__global__ void __launch_bounds__(512, 1) lstm_mma()
{
    extern __shared__ __align__(16) unsigned smem_u[];
    unsigned* hs  = smem_u;                          // [512][HP2]
    float*    Ds  = (float*)(smem_u + HS_FULL);      // [kh][64*DS_P]
    float*    hnS = Ds + DS_SZ;                      // [16][64]

    const int tid  = threadIdx.x;
    const int cta  = blockIdx.x;
    const int w    = tid >> 5, lane = tid & 31;
    const int g    = lane >> 2, tig = lane & 3;
    const int kh   = w >> 3;             // k-half 0/1
    const int cbw  = (w >> 2) & 1;       // m-half (32-col block) 0/1
    const int n0   = (w & 3) * 16;       // n-group
    const int pb   = tid & 63;           // pointwise batch
    const int jl   = tid >> 6;           // pointwise local j (0..7; also jl+8)
    const uint4* Af0 = d_Afh + (((size_t)(cta * 2 + cbw) * 2 + 0) * 64) * 32 + lane;
    const uint4* Af1 = d_Afh + (((size_t)(cta * 2 + cbw) * 2 + 1) * 64) * 32 + lane;
    const unsigned hs_base = (unsigned)__cvta_generic_to_shared(hs);
    float cs[2] = {0.f, 0.f};

    // prefetch xg for t = 0 (2 j per thread)
    float xgA[4], xgB[4];
#pragma unroll
    for (int q = 0; q < 4; q++) {
        xgA[q] = d_xg[(((size_t)0 * Hh + cta * 16 + jl) * 4 + q) * Bb + pb];
        xgB[q] = d_xg[(((size_t)0 * Hh + cta * 16 + jl + 8) * 4 + q) * Bb + pb];
    }

    for (int t = 0; t < Tt; t++) {
        const unsigned* hcur = d_h2h + (size_t)(t & 1) * (512 * Bb);
        unsigned*       hnxt = d_h2h + (size_t)((t + 1) & 1) * (512 * Bb);

        // ---- stage full h via cp.async: 8192 uint4, 16 per thread ----
#pragma unroll
        for (int p = 0; p < 16; p++) {
            int idx = p * 512 + tid;
            unsigned dst = hs_base + ((idx >> 4) * HP2 + (idx & 15) * 4) * 4;
            asm volatile("cp.async.cg.shared.global [%0], [%1], 16;"
                         :: "r"(dst), "l"((const uint4*)hcur + idx) : "memory");
        }
        asm volatile("cp.async.commit_group;" ::: "memory");
        asm volatile("cp.async.wait_group 0;" ::: "memory");
        __syncthreads();

        // ---- 32 k16 per warp (its half), both m-strips of its cbw ----
        float accA0[4] = {0.f, 0.f, 0.f, 0.f};   // ms0, n-group 0
        float accA1[4] = {0.f, 0.f, 0.f, 0.f};   // ms0, n-group 1
        float accB0[4] = {0.f, 0.f, 0.f, 0.f};   // ms1, n-group 0
        float accB1[4] = {0.f, 0.f, 0.f, 0.f};   // ms1, n-group 1
#pragma unroll 8
        for (int i = 0; i < 32; i++) {
            const int kk = kh * 32 + i;
            uint4 a0 = __ldg(&Af0[kk * 32]);
            uint4 a1 = __ldg(&Af1[kk * 32]);
            const int rb = kk * 8;
            unsigned b0 = hs[(rb + tig) * HP2 + n0 + g];
            unsigned b1 = hs[(rb + tig + 4) * HP2 + n0 + g];
            unsigned b2 = hs[(rb + tig) * HP2 + n0 + 8 + g];
            unsigned b3 = hs[(rb + tig + 4) * HP2 + n0 + 8 + g];
            MMA_F16(accA0, a0.x, a0.y, a0.z, a0.w, b0, b1);
            MMA_F16(accA1, a0.x, a0.y, a0.z, a0.w, b2, b3);
            MMA_F16(accB0, a1.x, a1.y, a1.z, a1.w, b0, b1);
            MMA_F16(accB1, a1.x, a1.y, a1.z, a1.w, b2, b3);
        }

        // D fragments -> per-half smem buffer (rows = local m 0..63)
        {
            float* D = Ds + kh * DS_H;
            int r1 = cbw * 32 + g,  r2 = r1 + 8;      // ms0
            int r3 = cbw * 32 + 16 + g, r4 = r3 + 8;  // ms1
            *(float2*)&D[r1 * DS_P + n0 + tig * 2]     = make_float2(accA0[0], accA0[1]);
            *(float2*)&D[r2 * DS_P + n0 + tig * 2]     = make_float2(accA0[2], accA0[3]);
            *(float2*)&D[r1 * DS_P + n0 + 8 + tig * 2] = make_float2(accA1[0], accA1[1]);
            *(float2*)&D[r2 * DS_P + n0 + 8 + tig * 2] = make_float2(accA1[2], accA1[3]);
            *(float2*)&D[r3 * DS_P + n0 + tig * 2]     = make_float2(accB0[0], accB0[1]);
            *(float2*)&D[r4 * DS_P + n0 + tig * 2]     = make_float2(accB0[2], accB0[3]);
            *(float2*)&D[r3 * DS_P + n0 + 8 + tig * 2] = make_float2(accB1[0], accB1[1]);
            *(float2*)&D[r4 * DS_P + n0 + 8 + tig * 2] = make_float2(accB1[2], accB1[3]);
        }
        __syncthreads();

        // pointwise: 2 (j, b) pairs per thread (jl and jl+8); sum the 2 halves
        float hnA, hnB;
#pragma unroll
        for (int pp = 0; pp < 2; pp++) {
            int jj = jl + pp * 8;                    // local j 0..15
            const float* xf = pp ? xgB : xgA;
            float gt[4];
#pragma unroll
            for (int q = 0; q < 4; q++) {
                int off = (jj * 4 + q) * DS_P + pb;  // D row = jj*4+q (0..63)
                gt[q] = Ds[off] + Ds[DS_H + off] + xf[q];
            }
            float si = sigm(gt[0]), sf = sigm(gt[1]);
            float sg = sigm(gt[2]), so = sigm(gt[3]);
            float cn = cs[pp] * sf + si * sg;        // NOTE: sigmoid cell gate (per ref)
            cs[pp] = cn;
            float hv = so * tanh_fast(cn);
            if (pp) hnB = hv; else hnA = hv;
            hnS[jj * 64 + pb] = hv;
        }
        __syncthreads();
        // 512 threads: one half2 h store each (16 j -> 8 rows x 64 b)
        {
            int jp = tid >> 6, b = tid & 63;         // jp 0..7
            __stcg(&hnxt[(cta * 8 + jp) * 64 + b],
                   pkh2(hnS[(2 * jp) * 64 + b], hnS[(2 * jp + 1) * 64 + b]));
        }
        __syncthreads();

        // ---- split barrier: arrive, do lazy work, wait ----
        if (tid == 0)
            asm volatile("red.release.gpu.global.add.u32 [%0], 1;"
                         :: "l"(&d_bcount) : "memory");
        d_hsJ[((size_t)(cta * 16 + jl) * Tt + t) * 64 + pb] = hnA;
        d_hsJ[((size_t)(cta * 16 + jl + 8) * Tt + t) * 64 + pb] = hnB;
        if (t + 1 < Tt) {
#pragma unroll
            for (int q = 0; q < 4; q++) {
                xgA[q] = d_xg[(((size_t)(t + 1) * Hh + cta * 16 + jl) * 4 + q) * Bb + pb];
                xgB[q] = d_xg[(((size_t)(t + 1) * Hh + cta * 16 + jl + 8) * 4 + q) * Bb + pb];
            }
        }
        if (tid == 0) {
            unsigned target = (unsigned)NCTA * (t + 1);
            unsigned c;
            do {
                asm volatile("ld.acquire.gpu.global.u32 %0, [%1];"
                             : "=r"(c) : "l"(&d_bcount) : "memory");
            } while (c < target);
        }
        __syncthreads();
    }
}

// ---------------- GEMM 3 (tf32 mma): outT[d][m'] = Wout . hs --------------------
#define HS_P 72
__global__ void __launch_bounds__(256) gemm_out_mma()
{
    __shared__ __align__(16) float hsm[2][64 * HS_P];
    const int tid = threadIdx.x, w = tid >> 5, lane = tid & 31;
    const int g = lane >> 2, tig = lane & 3;
    const int t = blockIdx.x;
    const int lk = tid >> 4, lf = tid & 15;
    const float4* Af1 = (const float4*)d_Wof + (size_t)w * 128 * 32 + lane;
    const float4* Af2 = (const float4*)d_Wof + (size_t)(w + 8) * 128 * 32 + lane;

    float acc[2][8][4];
#pragma unroll
    for (int sh = 0; sh < 2; sh++)
#pragma unroll
        for (int nbq = 0; nbq < 8; nbq++)
#pragma unroll
            for (int q = 0; q < 4; q++) acc[sh][nbq][q] = 0.f;

    float4 st[4];
#pragma unroll
    for (int p = 0; p < 4; p++) {
        int k = p * 16 + lk;
        st[p] = __ldcg((const float4*)&d_hsJ[((size_t)k * Tt + t) * 64 + lf * 4]);
    }

#pragma unroll 1
    for (int ch = 0; ch < 16; ch++) {
        const int buf = ch & 1;
#pragma unroll
        for (int p = 0; p < 4; p++)
            *(float4*)&hsm[buf][(p * 16 + lk) * HS_P + lf * 4] = st[p];
        __syncthreads();
        if (ch < 15) {
#pragma unroll
            for (int p = 0; p < 4; p++) {
                int k = (ch + 1) * 64 + p * 16 + lk;
                st[p] = __ldcg((const float4*)&d_hsJ[((size_t)k * Tt + t) * 64 + lf * 4]);
            }
        }
#pragma unroll
        for (int k8 = 0; k8 < 8; k8++) {
            const int kg = ch * 8 + k8;
            const int kl = k8 * 8;
            float4 af1 = __ldg(&Af1[kg * 32]);
            float4 af2 = __ldg(&Af2[kg * 32]);
#pragma unroll
            for (int nbq = 0; nbq < 8; nbq++) {
                unsigned b0 = tf32r(hsm[buf][(kl + tig) * HS_P + nbq * 8 + g]);
                unsigned b1 = tf32r(hsm[buf][(kl + tig + 4) * HS_P + nbq * 8 + g]);
                MMA_TF32(acc[0][nbq], __float_as_uint(af1.x), __float_as_uint(af1.y),
                         __float_as_uint(af1.z), __float_as_uint(af1.w), b0, b1);
                MMA_TF32(acc[1][nbq], __float_as_uint(af2.x), __float_as_uint(af2.y),
                         __float_as_uint(af2.z), __float_as_uint(af2.w), b0, b1);
            }
        }
        __syncthreads();
    }

#pragma unroll
    for (int sh = 0; sh < 2; sh++) {
        int dbase = (sh ? (w + 8) : w) * 16;
        int d1 = dbase + g, d2 = d1 + 8;
#pragma unroll
        for (int nbq = 0; nbq < 8; nbq++) {
            int bcol = nbq * 8 + tig * 2;
            *(float2*)&d_outT[(size_t)d1 * Mm + t * 64 + bcol] =
                make_float2(acc[sh][nbq][0], acc[sh][nbq][1]);
            *(float2*)&d_outT[(size_t)d2 * Mm + t * 64 + bcol] =
                make_float2(acc[sh][nbq][2], acc[sh][nbq][3]);
        }
    }
}

// ---------------- hidden = tanh(hs), [j][m'] -> [b][t][j] ----------------------
__global__ void tanhT_k(float* __restrict__ outH)
{
    __shared__ float tile[32][33];
    int m0 = blockIdx.x * 32;
    int j0 = blockIdx.y * 32;
    int tx = threadIdx.x, ty = threadIdx.y;
#pragma unroll
    for (int i = 0; i < 32; i += 8)
        tile[ty + i][tx] = d_hsJ[(size_t)(j0 + ty + i) * Mm + m0 + tx];
    __syncthreads();
    int t0 = m0 >> 6;
    int bbase = m0 & 63;
#pragma unroll
    for (int i = 0; i < 32; i += 8) {
        int mp = ty + i;
        int b = bbase + mp;
        outH[((size_t)b * Tt + t0) * Hh + j0 + tx] = tanh_ap(tile[tx][mp]);
    }
}

// ---------------- out = outT^T + bias: [d][m'] -> [b][t][d] ---------------------
__global__ void outT_k(const float* __restrict__ bo, float* __restrict__ outp)
{
    __shared__ float tile[32][33];
    int m0 = blockIdx.x * 32;
    int d0 = blockIdx.y * 32;
    int tx = threadIdx.x, ty = threadIdx.y;
#pragma unroll
    for (int i = 0; i < 32; i += 8)
        tile[ty + i][tx] = d_outT[(size_t)(d0 + ty + i) * Mm + m0 + tx];
    __syncthreads();
    int t0 = m0 >> 6;
    int bbase = m0 & 63;
    float bv = bo[d0 + tx];
#pragma unroll
    for (int i = 0; i < 32; i += 8) {
        int b = bbase + ty + i;
        outp[((size_t)b * Tt + t0) * Dd + d0 + tx] = tile[tx][ty + i] + bv;
    }
}

// ---------------- launch --------------------------------------------------------
extern "C" void kernel_launch(void* const* d_in, const int* in_sizes, int n_in,
                              void* d_out, int out_size)
{
    (void)in_sizes; (void)n_in; (void)out_size;
    const float* inp = (const float*)d_in[0];
    const float* Wx  = (const float*)d_in[1];
    const float* bx  = (const float*)d_in[2];
    const float* Wh  = (const float*)d_in[3];
    const float* bh  = (const float*)d_in[4];
    const float* Wo  = (const float*)d_in[5];
    const float* bo  = (const float*)d_in[6];
    float* out = (float*)d_out;
    float* outHidden = out + (size_t)Bb * Tt * Dd;

    const int xg_smem = 2 * 64 * XPH * sizeof(unsigned short);  // 67,584 B
    cudaFuncSetAttribute(gemm_xg_mma,
                         cudaFuncAttributeMaxDynamicSharedMemorySize, xg_smem);
    const int lstm_smem = (HS_FULL + DS_SZ + 16 * 64) * 4;      // ~183 KB
    cudaFuncSetAttribute(lstm_mma,
                         cudaFuncAttributeMaxDynamicSharedMemorySize, lstm_smem);

    init_k<<<256, 256>>>();                                  // #1 (also resets barrier)
    pack_all<<<2816, 256>>>(Wh, Wx, Wo);                     // #2
    gemm_xg_mma<<<dim3(32, 4), 256, xg_smem>>>(inp, bx, bh); // #3
    lstm_mma<<<NCTA, 512, lstm_smem>>>();                    // #4 -> profiled
    gemm_out_mma<<<Tt, 256>>>();                             // #5
    tanhT_k<<<dim3(Mm / 32, Hh / 32), dim3(32, 8)>>>(outHidden);
    outT_k<<<dim3(Mm / 32, Dd / 32), dim3(32, 8)>>>(bo, out);
}

// round 17
// speedup vs baseline: 1.2162x; 1.2162x over previous
#include <cuda_runtime.h>
#include <cuda_fp16.h>
#include <math.h>

// Problem dims
#define Bb   64
#define Tt   512
#define Dd   256
#define Hh   1024
#define Gg   4096          // 4*H
#define Mm   32768         // B*T
#define NCTA 128

// ---------------- scratch (__device__ globals; no dynamic allocation) ----------
__device__ float d_xg[(size_t)Tt * Gg * Bb];      // [t][m=j*4+g][b]   512 MB
__device__ uint4 d_Afh[(size_t)NCTA * 2 * 64 * 32];   // Wh fp16 A-frags, 8 MB
__device__ uint4 d_Axfh[(size_t)32 * 8 * 16 * 32];    // Wx fp16 A-frags, 2 MB
__device__ float d_Wof[(size_t)Dd * Hh];          // Wout tf32 A-fragments, 1 MB
__device__ float d_hsJ[(size_t)Hh * Mm];          // [j][m'] , m'=t*64+b   128 MB
__device__ float d_outT[(size_t)Dd * Mm];         // out head, [d][m']     32 MB
__device__ unsigned d_h2h[2 * 512 * Bb];          // double-buffered h, half2 [buf][k/2][b]
__device__ unsigned d_bcount;
__device__ unsigned d_epoch;

__device__ __forceinline__ unsigned tf32r(float x)
{
    unsigned u;
    asm("cvt.rna.tf32.f32 %0, %1;" : "=r"(u) : "f"(x));
    return u;
}
__device__ __forceinline__ float tanh_ap(float x)
{
    float y;
    asm("tanh.approx.f32 %0, %1;" : "=f"(y) : "f"(x));
    return y;
}
__device__ __forceinline__ unsigned pkh2(float lo, float hi)
{
    __half2 h = __floats2half2_rn(lo, hi);
    return *(unsigned*)&h;
}
// fast (MUFU) sigmoid / tanh: rel err ~2^-21, negligible vs fp16-h noise
__device__ __forceinline__ float sigm(float x)
{
    return __fdividef(1.f, 1.f + __expf(-x));
}
__device__ __forceinline__ float tanh_fast(float x)
{
    return __fdividef(2.f, 1.f + __expf(-2.f * x)) - 1.f;
}

// tf32 mma: D(m16n8) += A(m16k8) * B(k8n8)
#define MMA_TF32(d, a0, a1, a2, a3, b0, b1)                                     \
    asm volatile("mma.sync.aligned.m16n8k8.row.col.f32.tf32.tf32.f32 "          \
                 "{%0,%1,%2,%3}, {%4,%5,%6,%7}, {%8,%9}, {%0,%1,%2,%3};"        \
                 : "+f"(d[0]), "+f"(d[1]), "+f"(d[2]), "+f"(d[3])               \
                 : "r"(a0), "r"(a1), "r"(a2), "r"(a3), "r"(b0), "r"(b1))

// fp16 mma: D(m16n8) += A(m16k16) * B(k16n8), fp32 accum
#define MMA_F16(d, a0, a1, a2, a3, b0, b1)                                      \
    asm volatile("mma.sync.aligned.m16n8k16.row.col.f32.f16.f16.f32 "           \
                 "{%0,%1,%2,%3}, {%4,%5,%6,%7}, {%8,%9}, {%0,%1,%2,%3};"        \
                 : "+f"(d[0]), "+f"(d[1]), "+f"(d[2]), "+f"(d[3])               \
                 : "r"(a0), "r"(a1), "r"(a2), "r"(a3), "r"(b0), "r"(b1))

// ---------------- init: zero h state, reset barrier -----------------------------
__global__ void init_k()
{
    int i = blockIdx.x * blockDim.x + threadIdx.x;
    if (i < 2 * 512 * Bb) d_h2h[i] = 0u;
    if (i == 0) { d_bcount = 0u; d_epoch = 0u; }
}

// ---------------- combined weight-fragment packing ------------------------------
// blocks [0,2048): Wh fp16   [2048,2560): Wx fp16   [2560,2816): Wout tf32
__global__ void pack_all(const float* __restrict__ Wh, const float* __restrict__ Wx,
                         const float* __restrict__ Wo)
{
    int blk = blockIdx.x;
    if (blk < 2048) {
        // Wh fp16 A frag: uint4 i = ((cb*2+ms)*64 + k16)*32 + lane
        size_t i = (size_t)blk * 256 + threadIdx.x;   // 524,288 total
        int lane = i & 31;
        int k16  = (i >> 5) & 63;
        int ms   = (i >> 11) & 1;
        int cb   = (int)(i >> 12);
        int g = lane >> 2, tig = lane & 3;
        int m1 = ms * 16 + g, m2 = m1 + 8;
        int r1 = (m1 & 3) * Hh + cb * 8 + (m1 >> 2);
        int r2 = (m2 & 3) * Hh + cb * 8 + (m2 >> 2);
        int k0 = k16 * 16 + tig * 2;
        uint4 v;
        v.x = pkh2(Wh[(size_t)r1 * Hh + k0],     Wh[(size_t)r1 * Hh + k0 + 1]);
        v.y = pkh2(Wh[(size_t)r2 * Hh + k0],     Wh[(size_t)r2 * Hh + k0 + 1]);
        v.z = pkh2(Wh[(size_t)r1 * Hh + k0 + 8], Wh[(size_t)r1 * Hh + k0 + 9]);
        v.w = pkh2(Wh[(size_t)r2 * Hh + k0 + 8], Wh[(size_t)r2 * Hh + k0 + 9]);
        d_Afh[i] = v;
    } else if (blk < 2560) {
        // Wx fp16 A frag: uint4 i = ((gb*8+ws)*16 + k16)*32 + lane
        size_t i = (size_t)(blk - 2048) * 256 + threadIdx.x;  // 131,072 total
        int lane = i & 31;
        int k16  = (i >> 5) & 15;
        int ws   = (i >> 9) & 7;
        int gb   = (int)(i >> 12);
        int g = lane >> 2, tig = lane & 3;
        int m1 = gb * 128 + ws * 16 + g, m2 = m1 + 8;
        int r1 = (m1 & 3) * Hh + (m1 >> 2);
        int r2 = (m2 & 3) * Hh + (m2 >> 2);
        int k0 = k16 * 16 + tig * 2;
        uint4 v;
        v.x = pkh2(Wx[(size_t)r1 * Dd + k0],     Wx[(size_t)r1 * Dd + k0 + 1]);
        v.y = pkh2(Wx[(size_t)r2 * Dd + k0],     Wx[(size_t)r2 * Dd + k0 + 1]);
        v.z = pkh2(Wx[(size_t)r1 * Dd + k0 + 8], Wx[(size_t)r1 * Dd + k0 + 9]);
        v.w = pkh2(Wx[(size_t)r2 * Dd + k0 + 8], Wx[(size_t)r2 * Dd + k0 + 9]);
        d_Axfh[i] = v;
    } else {
        size_t i = (size_t)(blk - 2560) * 256 + threadIdx.x;
        int lane = i & 31;
        int k8   = (i >> 5) & 127;
        int s    = (int)(i >> 12);
        int g = lane >> 2, tig = lane & 3;
        int d1 = s * 16 + g, d2 = d1 + 8;
        int k0 = k8 * 8;
        float4 v;
        v.x = __uint_as_float(tf32r(Wo[(size_t)d1 * Hh + k0 + tig]));
        v.y = __uint_as_float(tf32r(Wo[(size_t)d2 * Hh + k0 + tig]));
        v.z = __uint_as_float(tf32r(Wo[(size_t)d1 * Hh + k0 + tig + 4]));
        v.w = __uint_as_float(tf32r(Wo[(size_t)d2 * Hh + k0 + tig + 4]));
        ((float4*)d_Wof)[i] = v;
    }
}

// ---------------- GEMM 1 (fp16 mma): xg[t][m][b] = inputs . Wx^T + bx + bh ------
// Inputs staged as fp16 [b][k], row = 256 halfs, PITCH 264 halfs.
#define XPH 264
__global__ void __launch_bounds__(256) gemm_xg_mma(
    const float* __restrict__ inp, const float* __restrict__ bx,
    const float* __restrict__ bh)
{
    extern __shared__ __align__(16) unsigned short hsmx[];   // 2 * 64 * XPH halfs
    const int tid = threadIdx.x, w = tid >> 5, lane = tid & 31;
    const int g = lane >> 2, tig = lane & 3;
    const int gb = blockIdx.x;
    const int m1 = gb * 128 + w * 16 + g, m2 = m1 + 8;
    const int r1 = (m1 & 3) * Hh + (m1 >> 2), r2 = (m2 & 3) * Hh + (m2 >> 2);
    const float bias1 = bx[r1] + bh[r1];
    const float bias2 = bx[r2] + bh[r2];
    const uint4* Af = d_Axfh + ((size_t)(gb * 8 + w) * 16) * 32 + lane;
    const int brow = w * 8 + (lane >> 2);
    const int bq = lane & 3;

    for (int t0 = blockIdx.y * 2; t0 < Tt; t0 += 8) {
#pragma unroll
        for (int sl = 0; sl < 2; sl++) {
            const float4* src = (const float4*)(inp + ((size_t)brow * Tt + t0 + sl) * Dd);
            unsigned short* dst = hsmx + sl * 64 * XPH + brow * XPH;
#pragma unroll
            for (int i2 = 0; i2 < 16; i2++) {
                float4 v = __ldg(&src[i2 * 4 + bq]);
                uint2 p;
                p.x = pkh2(v.x, v.y);
                p.y = pkh2(v.z, v.w);
                *(uint2*)&dst[(i2 * 4 + bq) * 4] = p;
            }
        }
        __syncthreads();

        float acc[2][8][4];
#pragma unroll
        for (int sl = 0; sl < 2; sl++)
#pragma unroll
            for (int nb = 0; nb < 8; nb++)
#pragma unroll
                for (int q = 0; q < 4; q++) acc[sl][nb][q] = 0.f;

#pragma unroll 4
        for (int k16 = 0; k16 < 16; k16++) {
            uint4 a4 = __ldg(&Af[k16 * 32]);
            const int k0 = k16 * 16;
#pragma unroll
            for (int nb = 0; nb < 8; nb++) {
#pragma unroll
                for (int sl = 0; sl < 2; sl++) {
                    const unsigned short* bp =
                        hsmx + sl * 64 * XPH + (nb * 8 + g) * XPH + k0 + tig * 2;
                    unsigned b0 = *(const unsigned*)bp;
                    unsigned b1 = *(const unsigned*)(bp + 8);
                    MMA_F16(acc[sl][nb], a4.x, a4.y, a4.z, a4.w, b0, b1);
                }
            }
        }
#pragma unroll
        for (int sl = 0; sl < 2; sl++) {
            int t = t0 + sl;
#pragma unroll
            for (int nb = 0; nb < 8; nb++) {
                *(float2*)&d_xg[((size_t)t * Gg + m1) * 64 + nb * 8 + tig * 2] =
                    make_float2(acc[sl][nb][0] + bias1, acc[sl][nb][1] + bias1);
                *(float2*)&d_xg[((size_t)t * Gg + m2) * 64 + nb * 8 + tig * 2] =
                    make_float2(acc[sl][nb][2] + bias2, acc[sl][nb][3] + bias2);
            }
        }
        __syncthreads();
    }
}

// ---------------- persistent LSTM recurrence (fp16 mma, R15 + chain cuts) -------
// 128 CTAs x 512 thr.  CTA owns 32 gate-cols, N=64, K=1024.  kq-split warps.
// Chain cuts vs R15: (a) pointwise by 256 threads owning ADJACENT j-pairs ->
// direct half2 h store, no smem exchange, one less sync; (b) epoch barrier:
// arrivals on d_bcount, last arriver writes d_epoch (single-writer poll line).
#define HP2 72
#define HS_FULL (512 * HP2)                  // unsigned words (144 KB)
#define DS_P 68
#define DS_Q (32 * DS_P)                     // floats per quarter buffer
#define DS_SZ (4 * DS_Q)                     // floats
__global__ void __launch_bounds__(512, 1) lstm_mma()
{
    extern __shared__ __align__(16) unsigned smem_u[];
    unsigned* hs  = smem_u;                          // [512][HP2]
    float*    Ds  = (float*)(smem_u + HS_FULL);      // [kq][32*DS_P]

    const int tid  = threadIdx.x;
    const int cta  = blockIdx.x;
    const int w    = tid >> 5, lane = tid & 31;
    const int g    = lane >> 2, tig = lane & 3;
    const int kq   = w >> 2;             // k-quarter 0..3
    const int n0   = (w & 3) * 16;       // n-group
    const int pb   = tid & 63;           // pointwise batch
    const int jp   = tid >> 6;           // pointwise j-pair index (0..3 for tid<256)
    const uint4* Af0 = d_Afh + ((size_t)(cta * 2 + 0) * 64) * 32 + lane;
    const uint4* Af1 = d_Afh + ((size_t)(cta * 2 + 1) * 64) * 32 + lane;
    const unsigned hs_base = (unsigned)__cvta_generic_to_shared(hs);
    float cs[2] = {0.f, 0.f};

    // prefetch xg for t = 0 (tid < 256: two adjacent j)
    float xgA[4], xgB[4];
    if (tid < 256) {
#pragma unroll
        for (int q = 0; q < 4; q++) {
            xgA[q] = d_xg[(((size_t)0 * Hh + cta * 8 + 2 * jp) * 4 + q) * Bb + pb];
            xgB[q] = d_xg[(((size_t)0 * Hh + cta * 8 + 2 * jp + 1) * 4 + q) * Bb + pb];
        }
    }

    for (int t = 0; t < Tt; t++) {
        const unsigned* hcur = d_h2h + (size_t)(t & 1) * (512 * Bb);
        unsigned*       hnxt = d_h2h + (size_t)((t + 1) & 1) * (512 * Bb);

        // ---- stage full h via cp.async: 8192 uint4, 16 per thread ----
#pragma unroll
        for (int p = 0; p < 16; p++) {
            int idx = p * 512 + tid;
            unsigned dst = hs_base + ((idx >> 4) * HP2 + (idx & 15) * 4) * 4;
            asm volatile("cp.async.cg.shared.global [%0], [%1], 16;"
                         :: "r"(dst), "l"((const uint4*)hcur + idx) : "memory");
        }
        asm volatile("cp.async.commit_group;" ::: "memory");
        asm volatile("cp.async.wait_group 0;" ::: "memory");
        __syncthreads();

        // ---- 16 k16 per warp (its quarter), both m-strips, B loaded once ----
        float accA0[4] = {0.f, 0.f, 0.f, 0.f};
        float accA1[4] = {0.f, 0.f, 0.f, 0.f};
        float accB0[4] = {0.f, 0.f, 0.f, 0.f};
        float accB1[4] = {0.f, 0.f, 0.f, 0.f};
#pragma unroll 8
        for (int i = 0; i < 16; i++) {
            const int kk = kq * 16 + i;
            uint4 a0 = __ldg(&Af0[kk * 32]);
            uint4 a1 = __ldg(&Af1[kk * 32]);
            const int rb = kk * 8;
            unsigned b0 = hs[(rb + tig) * HP2 + n0 + g];
            unsigned b1 = hs[(rb + tig + 4) * HP2 + n0 + g];
            unsigned b2 = hs[(rb + tig) * HP2 + n0 + 8 + g];
            unsigned b3 = hs[(rb + tig + 4) * HP2 + n0 + 8 + g];
            MMA_F16(accA0, a0.x, a0.y, a0.z, a0.w, b0, b1);
            MMA_F16(accA1, a0.x, a0.y, a0.z, a0.w, b2, b3);
            MMA_F16(accB0, a1.x, a1.y, a1.z, a1.w, b0, b1);
            MMA_F16(accB1, a1.x, a1.y, a1.z, a1.w, b2, b3);
        }

        // D fragments -> per-quarter smem buffer (rows = local m, cols = batch)
        {
            float* D = Ds + kq * DS_Q;
            int r1 = g, r2 = g + 8, r3 = g + 16, r4 = g + 24;
            *(float2*)&D[r1 * DS_P + n0 + tig * 2]     = make_float2(accA0[0], accA0[1]);
            *(float2*)&D[r2 * DS_P + n0 + tig * 2]     = make_float2(accA0[2], accA0[3]);
            *(float2*)&D[r1 * DS_P + n0 + 8 + tig * 2] = make_float2(accA1[0], accA1[1]);
            *(float2*)&D[r2 * DS_P + n0 + 8 + tig * 2] = make_float2(accA1[2], accA1[3]);
            *(float2*)&D[r3 * DS_P + n0 + tig * 2]     = make_float2(accB0[0], accB0[1]);
            *(float2*)&D[r4 * DS_P + n0 + tig * 2]     = make_float2(accB0[2], accB0[3]);
            *(float2*)&D[r3 * DS_P + n0 + 8 + tig * 2] = make_float2(accB1[0], accB1[1]);
            *(float2*)&D[r4 * DS_P + n0 + 8 + tig * 2] = make_float2(accB1[2], accB1[3]);
        }
        __syncthreads();

        // pointwise (tid < 256): two adjacent j; direct half2 h store
        float hn0 = 0.f, hn1 = 0.f;
        if (tid < 256) {
#pragma unroll
            for (int pp = 0; pp < 2; pp++) {
                int jl = 2 * jp + pp;
                const float* xf = pp ? xgB : xgA;
                float gt[4];
#pragma unroll
                for (int q = 0; q < 4; q++) {
                    int off = (jl * 4 + q) * DS_P + pb;
                    gt[q] = Ds[off] + Ds[DS_Q + off] + Ds[2 * DS_Q + off]
                          + Ds[3 * DS_Q + off] + xf[q];
                }
                float si = sigm(gt[0]), sf = sigm(gt[1]);
                float sg = sigm(gt[2]), so = sigm(gt[3]);
                float cn = cs[pp] * sf + si * sg;    // NOTE: sigmoid cell gate (per ref)
                cs[pp] = cn;
                float hv = so * tanh_fast(cn);
                if (pp) hn1 = hv; else hn0 = hv;
            }
            __stcg(&hnxt[(cta * 4 + jp) * 64 + pb], pkh2(hn0, hn1));
        }
        __syncthreads();

        // ---- epoch barrier: arrive on d_bcount, last arriver writes d_epoch ----
        if (tid == 0) {
            unsigned old;
            asm volatile("atom.relaxed.gpu.global.add.u32 %0, [%1], 1;"
                         : "=r"(old) : "l"(&d_bcount) : "memory");
            if (old == (unsigned)NCTA * (t + 1) - 1)
                asm volatile("st.release.gpu.global.u32 [%0], %1;"
                             :: "l"(&d_epoch), "r"((unsigned)(t + 1)) : "memory");
        }
        // lazy work between arrive and wait
        if (tid < 256) {
            d_hsJ[((size_t)(cta * 8 + 2 * jp) * Tt + t) * 64 + pb] = hn0;
            d_hsJ[((size_t)(cta * 8 + 2 * jp + 1) * Tt + t) * 64 + pb] = hn1;
            if (t + 1 < Tt) {
#pragma unroll
                for (int q = 0; q < 4; q++) {
                    xgA[q] = d_xg[(((size_t)(t + 1) * Hh + cta * 8 + 2 * jp) * 4 + q) * Bb + pb];
                    xgB[q] = d_xg[(((size_t)(t + 1) * Hh + cta * 8 + 2 * jp + 1) * 4 + q) * Bb + pb];
                }
            }
        }
        if (tid == 0) {
            unsigned e;
            do {
                asm volatile("ld.acquire.gpu.global.u32 %0, [%1];"
                             : "=r"(e) : "l"(&d_epoch) : "memory");
            } while (e < (unsigned)(t + 1));
        }
        __syncthreads();
    }
}

// ---------------- GEMM 3 (tf32 mma): outT[d][m'] = Wout . hs --------------------
#define HS_P 72
__global__ void __launch_bounds__(256) gemm_out_mma()
{
    __shared__ __align__(16) float hsm[2][64 * HS_P];
    const int tid = threadIdx.x, w = tid >> 5, lane = tid & 31;
    const int g = lane >> 2, tig = lane & 3;
    const int t = blockIdx.x;
    const int lk = tid >> 4, lf = tid & 15;
    const float4* Af1 = (const float4*)d_Wof + (size_t)w * 128 * 32 + lane;
    const float4* Af2 = (const float4*)d_Wof + (size_t)(w + 8) * 128 * 32 + lane;

    float acc[2][8][4];
#pragma unroll
    for (int sh = 0; sh < 2; sh++)
#pragma unroll
        for (int nbq = 0; nbq < 8; nbq++)
#pragma unroll
            for (int q = 0; q < 4; q++) acc[sh][nbq][q] = 0.f;

    float4 st[4];
#pragma unroll
    for (int p = 0; p < 4; p++) {
        int k = p * 16 + lk;
        st[p] = __ldcg((const float4*)&d_hsJ[((size_t)k * Tt + t) * 64 + lf * 4]);
    }

#pragma unroll 1
    for (int ch = 0; ch < 16; ch++) {
        const int buf = ch & 1;
#pragma unroll
        for (int p = 0; p < 4; p++)
            *(float4*)&hsm[buf][(p * 16 + lk) * HS_P + lf * 4] = st[p];
        __syncthreads();
        if (ch < 15) {
#pragma unroll
            for (int p = 0; p < 4; p++) {
                int k = (ch + 1) * 64 + p * 16 + lk;
                st[p] = __ldcg((const float4*)&d_hsJ[((size_t)k * Tt + t) * 64 + lf * 4]);
            }
        }
#pragma unroll
        for (int k8 = 0; k8 < 8; k8++) {
            const int kg = ch * 8 + k8;
            const int kl = k8 * 8;
            float4 af1 = __ldg(&Af1[kg * 32]);
            float4 af2 = __ldg(&Af2[kg * 32]);
#pragma unroll
            for (int nbq = 0; nbq < 8; nbq++) {
                unsigned b0 = tf32r(hsm[buf][(kl + tig) * HS_P + nbq * 8 + g]);
                unsigned b1 = tf32r(hsm[buf][(kl + tig + 4) * HS_P + nbq * 8 + g]);
                MMA_TF32(acc[0][nbq], __float_as_uint(af1.x), __float_as_uint(af1.y),
                         __float_as_uint(af1.z), __float_as_uint(af1.w), b0, b1);
                MMA_TF32(acc[1][nbq], __float_as_uint(af2.x), __float_as_uint(af2.y),
                         __float_as_uint(af2.z), __float_as_uint(af2.w), b0, b1);
            }
        }
        __syncthreads();
    }

#pragma unroll
    for (int sh = 0; sh < 2; sh++) {
        int dbase = (sh ? (w + 8) : w) * 16;
        int d1 = dbase + g, d2 = d1 + 8;
#pragma unroll
        for (int nbq = 0; nbq < 8; nbq++) {
            int bcol = nbq * 8 + tig * 2;
            *(float2*)&d_outT[(size_t)d1 * Mm + t * 64 + bcol] =
                make_float2(acc[sh][nbq][0], acc[sh][nbq][1]);
            *(float2*)&d_outT[(size_t)d2 * Mm + t * 64 + bcol] =
                make_float2(acc[sh][nbq][2], acc[sh][nbq][3]);
        }
    }
}

// ---------------- hidden = tanh(hs), [j][m'] -> [b][t][j] ----------------------
__global__ void tanhT_k(float* __restrict__ outH)
{
    __shared__ float tile[32][33];
    int m0 = blockIdx.x * 32;
    int j0 = blockIdx.y * 32;
    int tx = threadIdx.x, ty = threadIdx.y;
#pragma unroll
    for (int i = 0; i < 32; i += 8)
        tile[ty + i][tx] = d_hsJ[(size_t)(j0 + ty + i) * Mm + m0 + tx];
    __syncthreads();
    int t0 = m0 >> 6;
    int bbase = m0 & 63;
#pragma unroll
    for (int i = 0; i < 32; i += 8) {
        int mp = ty + i;
        int b = bbase + mp;
        outH[((size_t)b * Tt + t0) * Hh + j0 + tx] = tanh_ap(tile[tx][mp]);
    }
}

// ---------------- out = outT^T + bias: [d][m'] -> [b][t][d] ---------------------
__global__ void outT_k(const float* __restrict__ bo, float* __restrict__ outp)
{
    __shared__ float tile[32][33];
    int m0 = blockIdx.x * 32;
    int d0 = blockIdx.y * 32;
    int tx = threadIdx.x, ty = threadIdx.y;
#pragma unroll
    for (int i = 0; i < 32; i += 8)
        tile[ty + i][tx] = d_outT[(size_t)(d0 + ty + i) * Mm + m0 + tx];
    __syncthreads();
    int t0 = m0 >> 6;
    int bbase = m0 & 63;
    float bv = bo[d0 + tx];
#pragma unroll
    for (int i = 0; i < 32; i += 8) {
        int b = bbase + ty + i;
        outp[((size_t)b * Tt + t0) * Dd + d0 + tx] = tile[tx][ty + i] + bv;
    }
}

// ---------------- launch --------------------------------------------------------
extern "C" void kernel_launch(void* const* d_in, const int* in_sizes, int n_in,
                              void* d_out, int out_size)
{
    (void)in_sizes; (void)n_in; (void)out_size;
    const float* inp = (const float*)d_in[0];
    const float* Wx  = (const float*)d_in[1];
    const float* bx  = (const float*)d_in[2];
    const float* Wh  = (const float*)d_in[3];
    const float* bh  = (const float*)d_in[4];
    const float* Wo  = (const float*)d_in[5];
    const float* bo  = (const float*)d_in[6];
    float* out = (float*)d_out;
    float* outHidden = out + (size_t)Bb * Tt * Dd;

    const int xg_smem = 2 * 64 * XPH * sizeof(unsigned short);  // 67,584 B
    cudaFuncSetAttribute(gemm_xg_mma,
                         cudaFuncAttributeMaxDynamicSharedMemorySize, xg_smem);
    const int lstm_smem = (HS_FULL + DS_SZ) * 4;                // ~182 KB
    cudaFuncSetAttribute(lstm_mma,
                         cudaFuncAttributeMaxDynamicSharedMemorySize, lstm_smem);

    init_k<<<256, 256>>>();                                  // #1 (also resets barrier)
    pack_all<<<2816, 256>>>(Wh, Wx, Wo);                     // #2
    gemm_xg_mma<<<dim3(32, 4), 256, xg_smem>>>(inp, bx, bh); // #3
    lstm_mma<<<NCTA, 512, lstm_smem>>>();                    // #4 -> profiled
    gemm_out_mma<<<Tt, 256>>>();                             // #5
    tanhT_k<<<dim3(Mm / 32, Hh / 32), dim3(32, 8)>>>(outHidden);
    outT_k<<<dim3(Mm / 32, Dd / 32), dim3(32, 8)>>>(bo, out);
}